// round 4
// baseline (speedup 1.0000x reference)
#include <cuda_runtime.h>
#include <cuda_bf16.h>
#include <cstdint>

#define RM 8192
#define RN 8192
#define D_DIM 256
#define TM 128          // CTA tile rows
#define TN 256          // CTA tile cols
#define TILES_M 64
#define NTILES 2048     // 64 x 32
#define STAGE_A (TM*128)            // 16 KB
#define STAGE_B (TN*128)            // 32 KB
#define STAGE_BYTES (STAGE_A+STAGE_B)
#define NSTAGE 4
#define SMEM0 1024
#define SMEM_TOTAL (SMEM0 + NSTAGE*STAGE_BYTES)   // 197632
#define MAIN_GRID 148
#define NTHREADS 256

__device__ __align__(1024) __nv_bfloat16 g_A[RM*D_DIM];   // 4 MB
__device__ __align__(1024) __nv_bfloat16 g_B[RN*D_DIM];   // 4 MB
__device__ float g_valid[RM];
__device__ double g_acc;

__device__ __forceinline__ uint32_t smem_u32(const void* p){
    uint32_t a; asm("{ .reg .u64 t; cvta.to.shared.u64 t, %1; cvt.u32.u64 %0, t; }":"=r"(a):"l"(p)); return a;
}
#define CPA16(d,s) asm volatile("cp.async.cg.shared.global [%0], [%1], 16;"::"r"(d),"l"(s):"memory")
#define CP_COMMIT() asm volatile("cp.async.commit_group;":::"memory")
#define CP_WAIT2()  asm volatile("cp.async.wait_group 2;":::"memory")

#define LDSM4(r0,r1,r2,r3,addr) \
    asm volatile("ldmatrix.sync.aligned.m8n8.x4.shared.b16 {%0,%1,%2,%3}, [%4];" \
        : "=r"(r0),"=r"(r1),"=r"(r2),"=r"(r3) : "r"(addr))

#define MMA16816(c,a,b0,b1) \
    asm volatile("mma.sync.aligned.m16n8k16.row.col.f32.bf16.bf16.f32 " \
        "{%0,%1,%2,%3},{%4,%5,%6,%7},{%8,%9},{%0,%1,%2,%3};" \
        : "+f"((c)[0]),"+f"((c)[1]),"+f"((c)[2]),"+f"((c)[3]) \
        : "r"((a)[0]),"r"((a)[1]),"r"((a)[2]),"r"((a)[3]),"r"(b0),"r"(b1))

// SW128 swizzle: for byte offset row*128 + off (off<128), swizzled = row*128 + (off ^ ((row&7)<<4))

__device__ __forceinline__ void load_chunk(int q, int tid, uint32_t sb, int bid, int grid){
    int lt = q>>2, kc = q&3;
    int t = bid + lt*grid;
    int tm = t & (TILES_M-1), tn = t>>6;
    uint32_t st  = sb + SMEM0 + (q&3)*STAGE_BYTES;   // A stage base (1024-aligned)
    uint32_t stB = st + STAGE_A;                      // B stage base (1024-aligned)
    const __nv_bfloat16* Ag = g_A + (size_t)(tm*TM)*D_DIM + kc*64;
    const __nv_bfloat16* Bg = g_B + (size_t)(tn*TN)*D_DIM + kc*64;
    // A: 128 rows x 8 x 16B  -> 1024 units; B: 256 rows x 8 -> 2048 units. 12 units/thread.
    #pragma unroll
    for(int j=0;j<4;j++){
        int u = tid + j*NTHREADS;               // 0..1023 : A
        int r = u>>3, c = u&7;
        uint32_t off = (c*16) ^ ((r&7)<<4);
        CPA16(st + r*128 + off, Ag + (size_t)r*D_DIM + c*8);
    }
    #pragma unroll
    for(int j=0;j<8;j++){
        int u = tid + j*NTHREADS;               // 0..2047 : B
        int r = u>>3, c = u&7;
        uint32_t off = (c*16) ^ ((r&7)<<4);
        CPA16(stB + r*128 + off, Bg + (size_t)r*D_DIM + c*8);
    }
}

__global__ void __launch_bounds__(NTHREADS,1) frag_main(){
    extern __shared__ char smem[];
    uint32_t sb = smem_u32(smem);
    int tid = threadIdx.x, wid = tid>>5, lane = tid&31;
    int bid = blockIdx.x, grid = gridDim.x;

    int warpM = wid & 1;          // 0..1  -> m offset 0/64
    int warpN = wid >> 1;         // 0..3  -> n offset 0/64/128/192
    int m0 = warpM*64, n0 = warpN*64;

    // per-lane ldmatrix base offsets (within stage, relative to stage base)
    // addr = stagebase + row*128 + ((ks*32 + (lane>>4)*16) ^ ((lane&7)<<4))
    uint32_t perm = (lane&7)<<4;
    uint32_t halfoff = (lane>>4)*16;
    uint32_t rowA[4], rowB[4];
    #pragma unroll
    for(int f=0;f<4;f++){
        rowA[f] = (m0 + f*16 + (lane&15))*128;
        rowB[f] = (n0 + f*16 + (lane&15))*128;
    }

    int ntl = 0;
    for(int t=bid;t<NTILES;t+=grid) ntl++;
    int nch = ntl*4;

    float c[4][8][4];
    #pragma unroll
    for(int i=0;i<4;i++)
        #pragma unroll
        for(int j=0;j<8;j++)
            #pragma unroll
            for(int k=0;k<4;k++) c[i][j][k] = 0.f;

    float acc = 0.f;

    for(int q=0;q<3;q++){
        if(q<nch) load_chunk(q, tid, sb, bid, grid);
        CP_COMMIT();
    }

    int q = 0, lt = 0;
    for(int t=bid;t<NTILES;t+=grid,lt++){
        int tm = t & (TILES_M-1), tn = t>>6;
        #pragma unroll
        for(int kc=0;kc<4;kc++,q++){
            CP_WAIT2();                 // chunk q resident
            __syncthreads();            // all warps done reading stage (q-1)&3
            if(q+3 < nch) load_chunk(q+3, tid, sb, bid, grid);
            CP_COMMIT();

            uint32_t stA = sb + SMEM0 + (q&3)*STAGE_BYTES;
            uint32_t stB = stA + STAGE_A;
            uint32_t a[2][4][4], b[2][4][4];
            // prefetch kstep 0
            {
                uint32_t kx = (0*32 + halfoff) ^ perm;
                #pragma unroll
                for(int f=0;f<4;f++) LDSM4(a[0][f][0],a[0][f][1],a[0][f][2],a[0][f][3], stA + rowA[f] + kx);
                #pragma unroll
                for(int f=0;f<4;f++) LDSM4(b[0][f][0],b[0][f][1],b[0][f][2],b[0][f][3], stB + rowB[f] + kx);
            }
            #pragma unroll
            for(int ks=0;ks<4;ks++){
                int cur = ks&1, nxt = cur^1;
                if(ks<3){
                    uint32_t kx = ((ks+1)*32 + halfoff) ^ perm;
                    #pragma unroll
                    for(int f=0;f<4;f++) LDSM4(a[nxt][f][0],a[nxt][f][1],a[nxt][f][2],a[nxt][f][3], stA + rowA[f] + kx);
                    #pragma unroll
                    for(int f=0;f<4;f++) LDSM4(b[nxt][f][0],b[nxt][f][1],b[nxt][f][2],b[nxt][f][3], stB + rowB[f] + kx);
                }
                #pragma unroll
                for(int mf=0;mf<4;mf++)
                    #pragma unroll
                    for(int nb=0;nb<4;nb++){
                        MMA16816(c[mf][2*nb],   a[cur][mf], b[cur][nb][0], b[cur][nb][2]);
                        MMA16816(c[mf][2*nb+1], a[cur][mf], b[cur][nb][1], b[cur][nb][3]);
                    }
            }
        }

        // ---- epilogue: masked relu-sum of this tile's C, then clear C ----
        #pragma unroll
        for(int mf=0;mf<4;mf++){
            int growf = tm*TM + m0 + mf*16;          // frag-uniform base row
            int rb = growf >> 5;                      // face batch (rows 16-aligned within 32-block)
            float v0 = g_valid[growf + (lane>>2)];
            float v1 = g_valid[growf + (lane>>2) + 8];
            float r0 = 0.f, r1 = 0.f;
            #pragma unroll
            for(int nb=0;nb<4;nb++){
                #pragma unroll
                for(int sub=0;sub<2;sub++){
                    int cb = (tn*TN + n0 + nb*16 + sub*8) >> 5;   // entity batch
                    float sgn = (cb==rb) ? -1.f : 1.f;
                    float* cc = c[mf][2*nb+sub];
                    r0 += fmaxf(fmaf(sgn, cc[0], 1.f), 0.f);
                    r0 += fmaxf(fmaf(sgn, cc[1], 1.f), 0.f);
                    r1 += fmaxf(fmaf(sgn, cc[2], 1.f), 0.f);
                    r1 += fmaxf(fmaf(sgn, cc[3], 1.f), 0.f);
                    cc[0]=0.f; cc[1]=0.f; cc[2]=0.f; cc[3]=0.f;
                }
            }
            acc += v0*r0 + v1*r1;
        }
    }

    // ---- reduce acc over CTA, one double atomic ----
    #pragma unroll
    for(int o=16;o;o>>=1) acc += __shfl_xor_sync(0xffffffffu, acc, o);
    __shared__ float red[8];
    if(lane==0) red[wid] = acc;
    __syncthreads();
    if(tid==0){
        double s = 0.0;
        #pragma unroll
        for(int w=0;w<8;w++) s += (double)red[w];
        atomicAdd(&g_acc, s);
    }
}

// ---- prep: fp32 -> bf16 + validity + acc clear ----
__global__ void frag_prep(const float* __restrict__ face, const float* __restrict__ ner){
    __shared__ float ws[8];
    int r = blockIdx.x, t = threadIdx.x;
    if(r==0 && t==0) g_acc = 0.0;
    if(r < RM){
        float v = face[(size_t)r*D_DIM + t];
        g_A[(size_t)r*D_DIM + t] = __float2bfloat16(v);
        float s = v;
        #pragma unroll
        for(int o=16;o;o>>=1) s += __shfl_xor_sync(0xffffffffu, s, o);
        if((t&31)==0) ws[t>>5] = s;
        __syncthreads();
        if(t==0){
            float tot = 0.f;
            #pragma unroll
            for(int w=0;w<8;w++) tot += ws[w];
            g_valid[r] = (tot != 0.f) ? 1.f : 0.f;
        }
    } else {
        int rr = r - RM;
        g_B[(size_t)rr*D_DIM + t] = __float2bfloat16(ner[(size_t)rr*D_DIM + t]);
    }
}

__global__ void frag_final(float* out){
    out[0] = (float)(g_acc / 256.0);
}

extern "C" void kernel_launch(void* const* d_in, const int* in_sizes, int n_in,
                              void* d_out, int out_size){
    const float* face = (const float*)d_in[0];
    const float* ner  = (const float*)d_in[1];
    float* out = (float*)d_out;

    cudaFuncSetAttribute(frag_main, cudaFuncAttributeMaxDynamicSharedMemorySize, SMEM_TOTAL);

    frag_prep<<<RM+RN, 256>>>(face, ner);
    frag_main<<<MAIN_GRID, NTHREADS, SMEM_TOTAL>>>();
    frag_final<<<1, 1>>>(out);
}

// round 5
// speedup vs baseline: 1.9224x; 1.9224x over previous
#include <cuda_runtime.h>
#include <cuda_bf16.h>
#include <cstdint>

#define RM 8192
#define RN 8192
#define DB 256           // bytes per row (int8, D=256)
#define TM 128
#define TN 256
#define TILES_M 64
#define NTILES 2048
#define STAGE_A (TM*128)             // 16 KB
#define STAGE_B (TN*128)             // 32 KB
#define STAGE_BYTES (STAGE_A+STAGE_B)
#define NSTAGE 4
#define SMEM0 1024
#define SMEM_TOTAL (SMEM0 + NSTAGE*STAGE_BYTES)
#define MAIN_GRID 148
#define NTHREADS 256
#define QSCALE 20.0f
#define INV_SCALE (1.0f/(QSCALE*QSCALE))

__device__ __align__(1024) signed char g_A[RM*DB];   // 2 MB
__device__ __align__(1024) signed char g_B[RN*DB];   // 2 MB
__device__ float g_valid[RM];
__device__ double g_acc;
__device__ unsigned g_done;

__device__ __forceinline__ uint32_t smem_u32(const void* p){
    uint32_t a; asm("{ .reg .u64 t; cvta.to.shared.u64 t, %1; cvt.u32.u64 %0, t; }":"=r"(a):"l"(p)); return a;
}
#define CPA16(d,s) asm volatile("cp.async.cg.shared.global [%0], [%1], 16;"::"r"(d),"l"(s):"memory")
#define CP_COMMIT() asm volatile("cp.async.commit_group;":::"memory")
#define CP_WAIT2()  asm volatile("cp.async.wait_group 2;":::"memory")

#define LDSM4(r0,r1,r2,r3,addr) \
    asm volatile("ldmatrix.sync.aligned.m8n8.x4.shared.b16 {%0,%1,%2,%3}, [%4];" \
        : "=r"(r0),"=r"(r1),"=r"(r2),"=r"(r3) : "r"(addr))

// int8 MMA: m16n8k32, s32 accum (exact)
#define MMAS8(c,a,b0,b1) \
    asm volatile("mma.sync.aligned.m16n8k32.row.col.s32.s8.s8.s32 " \
        "{%0,%1,%2,%3},{%4,%5,%6,%7},{%8,%9},{%0,%1,%2,%3};" \
        : "+r"((c)[0]),"+r"((c)[1]),"+r"((c)[2]),"+r"((c)[3]) \
        : "r"((a)[0]),"r"((a)[1]),"r"((a)[2]),"r"((a)[3]),"r"(b0),"r"(b1))

// Load one 128-byte K-chunk of an A(128row)+B(256row) tile into stage (q&3).
__device__ __forceinline__ void load_chunk(int q, int tid, uint32_t sb, int bid, int grid){
    int lt = q>>1, kc = q&1;
    int t = bid + lt*grid;
    int tm = t & (TILES_M-1), tn = t>>6;
    uint32_t st  = sb + SMEM0 + (q&3)*STAGE_BYTES;
    uint32_t stB = st + STAGE_A;
    const signed char* Ag = g_A + (size_t)(tm*TM)*DB + kc*128;
    const signed char* Bg = g_B + (size_t)(tn*TN)*DB + kc*128;
    #pragma unroll
    for(int j=0;j<4;j++){                       // A: 1024 16B units
        int u = tid + j*NTHREADS;
        int r = u>>3, c = u&7;
        uint32_t off = (c*16) ^ ((r&7)<<4);
        CPA16(st + r*128 + off, Ag + (size_t)r*DB + c*16);
    }
    #pragma unroll
    for(int j=0;j<8;j++){                       // B: 2048 16B units
        int u = tid + j*NTHREADS;
        int r = u>>3, c = u&7;
        uint32_t off = (c*16) ^ ((r&7)<<4);
        CPA16(stB + r*128 + off, Bg + (size_t)r*DB + c*16);
    }
}

__global__ void __launch_bounds__(NTHREADS,1) frag_main(float* out){
    extern __shared__ char smem[];
    uint32_t sb = smem_u32(smem);
    int tid = threadIdx.x, wid = tid>>5, lane = tid&31;
    int bid = blockIdx.x, grid = gridDim.x;

    int m0 = (wid & 1)*64, n0 = (wid >> 1)*64;

    uint32_t perm = (lane&7)<<4;
    uint32_t halfoff = (lane>>4)*16;
    uint32_t rowA[4], rowB[4];
    #pragma unroll
    for(int f=0;f<4;f++){
        rowA[f] = (m0 + f*16 + (lane&15))*128;
        rowB[f] = (n0 + f*16 + (lane&15))*128;
    }

    int ntl = 0;
    for(int t=bid;t<NTILES;t+=grid) ntl++;
    int nch = ntl*2;

    int c[4][8][4];
    #pragma unroll
    for(int i=0;i<4;i++)
        #pragma unroll
        for(int j=0;j<8;j++)
            #pragma unroll
            for(int k=0;k<4;k++) c[i][j][k] = 0;

    float acc = 0.f;

    for(int q=0;q<3;q++){
        if(q<nch) load_chunk(q, tid, sb, bid, grid);
        CP_COMMIT();
    }

    int q = 0, lt = 0;
    for(int t=bid;t<NTILES;t+=grid,lt++){
        int tm = t & (TILES_M-1), tn = t>>6;
        #pragma unroll
        for(int kc=0;kc<2;kc++,q++){
            CP_WAIT2();
            __syncthreads();
            if(q+3 < nch) load_chunk(q+3, tid, sb, bid, grid);
            CP_COMMIT();

            uint32_t stA = sb + SMEM0 + (q&3)*STAGE_BYTES;
            uint32_t stB = stA + STAGE_A;
            uint32_t a[2][4][4], b[2][4][4];
            {
                uint32_t kx = halfoff ^ perm;
                #pragma unroll
                for(int f=0;f<4;f++) LDSM4(a[0][f][0],a[0][f][1],a[0][f][2],a[0][f][3], stA + rowA[f] + kx);
                #pragma unroll
                for(int f=0;f<4;f++) LDSM4(b[0][f][0],b[0][f][1],b[0][f][2],b[0][f][3], stB + rowB[f] + kx);
            }
            #pragma unroll
            for(int ks=0;ks<4;ks++){            // 4 x K=32 per 128B chunk
                int cur = ks&1, nxt = cur^1;
                if(ks<3){
                    uint32_t kx = ((ks+1)*32 + halfoff) ^ perm;
                    #pragma unroll
                    for(int f=0;f<4;f++) LDSM4(a[nxt][f][0],a[nxt][f][1],a[nxt][f][2],a[nxt][f][3], stA + rowA[f] + kx);
                    #pragma unroll
                    for(int f=0;f<4;f++) LDSM4(b[nxt][f][0],b[nxt][f][1],b[nxt][f][2],b[nxt][f][3], stB + rowB[f] + kx);
                }
                #pragma unroll
                for(int mf=0;mf<4;mf++)
                    #pragma unroll
                    for(int nb=0;nb<4;nb++){
                        MMAS8(c[mf][2*nb],   a[cur][mf], (uint32_t)b[cur][nb][0], (uint32_t)b[cur][nb][2]);
                        MMAS8(c[mf][2*nb+1], a[cur][mf], (uint32_t)b[cur][nb][1], (uint32_t)b[cur][nb][3]);
                    }
            }
        }

        // epilogue: relu(1 +/- d) masked by row validity; accumulate, clear C
        #pragma unroll
        for(int mf=0;mf<4;mf++){
            int growf = tm*TM + m0 + mf*16;
            int rb = growf >> 5;
            float v0 = g_valid[growf + (lane>>2)];
            float v1 = g_valid[growf + (lane>>2) + 8];
            float r0 = 0.f, r1 = 0.f;
            #pragma unroll
            for(int nb=0;nb<4;nb++){
                #pragma unroll
                for(int sub=0;sub<2;sub++){
                    int cb = (tn*TN + n0 + nb*16 + sub*8) >> 5;
                    float sf = (cb==rb) ? -INV_SCALE : INV_SCALE;
                    int* cc = c[mf][2*nb+sub];
                    r0 += fmaxf(fmaf(sf, __int2float_rn(cc[0]), 1.f), 0.f);
                    r0 += fmaxf(fmaf(sf, __int2float_rn(cc[1]), 1.f), 0.f);
                    r1 += fmaxf(fmaf(sf, __int2float_rn(cc[2]), 1.f), 0.f);
                    r1 += fmaxf(fmaf(sf, __int2float_rn(cc[3]), 1.f), 0.f);
                    cc[0]=0; cc[1]=0; cc[2]=0; cc[3]=0;
                }
            }
            acc += v0*r0 + v1*r1;
        }
    }

    // CTA reduce + global accumulate + merged finalization
    #pragma unroll
    for(int o=16;o;o>>=1) acc += __shfl_xor_sync(0xffffffffu, acc, o);
    __shared__ float red[8];
    if(lane==0) red[wid] = acc;
    __syncthreads();
    if(tid==0){
        double s = 0.0;
        #pragma unroll
        for(int w=0;w<8;w++) s += (double)red[w];
        atomicAdd(&g_acc, s);
        __threadfence();
        unsigned prev = atomicAdd(&g_done, 1u);
        if(prev == gridDim.x - 1){
            __threadfence();
            double tot = *((volatile double*)&g_acc);
            out[0] = (float)(tot / 256.0);
        }
    }
}

// prep: fp32 -> int8 quantize (scale 20), validity mask, clear accumulators
__global__ void frag_prep(const float* __restrict__ face, const float* __restrict__ ner){
    int tid = threadIdx.x, wid = tid>>5, lane = tid&31;
    if(blockIdx.x==0 && tid==0){ g_acc = 0.0; g_done = 0u; }
    int row = blockIdx.x*8 + wid;                 // grid 2048 x 256 thr, warp per row
    bool isface = row < RM;
    const float* src = isface ? (face + (size_t)row*256) : (ner + (size_t)(row-RM)*256);
    signed char* dst = isface ? (g_A + (size_t)row*DB) : (g_B + (size_t)(row-RM)*DB);

    float4 v0 = ((const float4*)src)[lane];
    float4 v1 = ((const float4*)src)[lane+32];

    char4 q0, q1;
    #define QZ(x) (signed char)max(-127, min(127, __float2int_rn((x)*QSCALE)))
    q0.x=QZ(v0.x); q0.y=QZ(v0.y); q0.z=QZ(v0.z); q0.w=QZ(v0.w);
    q1.x=QZ(v1.x); q1.y=QZ(v1.y); q1.z=QZ(v1.z); q1.w=QZ(v1.w);
    #undef QZ
    ((char4*)dst)[lane]    = q0;
    ((char4*)dst)[lane+32] = q1;

    if(isface){
        float s = v0.x+v0.y+v0.z+v0.w + v1.x+v1.y+v1.z+v1.w;
        #pragma unroll
        for(int o=16;o;o>>=1) s += __shfl_xor_sync(0xffffffffu, s, o);
        if(lane==0) g_valid[row] = (s != 0.f) ? 1.f : 0.f;
    }
}

extern "C" void kernel_launch(void* const* d_in, const int* in_sizes, int n_in,
                              void* d_out, int out_size){
    const float* face = (const float*)d_in[0];
    const float* ner  = (const float*)d_in[1];
    float* out = (float*)d_out;

    cudaFuncSetAttribute(frag_main, cudaFuncAttributeMaxDynamicSharedMemorySize, SMEM_TOTAL);

    frag_prep<<<(RM+RN)/8, 256>>>(face, ner);
    frag_main<<<MAIN_GRID, NTHREADS, SMEM_TOTAL>>>(out);
}

// round 6
// speedup vs baseline: 1.9404x; 1.0093x over previous
#include <cuda_runtime.h>
#include <cuda_bf16.h>
#include <cstdint>

#define RM 8192
#define RN 8192
#define DB 256            // bytes per row (int8, D=256)
#define TM 128
#define TN 128
#define TILES_M 64
#define NTILES 4096       // 64 x 64
#define STAGE_A (TM*128)              // 16 KB
#define STAGE_B (TN*128)              // 16 KB
#define STAGE_BYTES (STAGE_A+STAGE_B) // 32 KB
#define NSTAGE 3
#define SMEM0 1024
#define SMEM_TOTAL (SMEM0 + NSTAGE*STAGE_BYTES)   // 99328
#define MAIN_GRID 296
#define NTHREADS 256
#define QSCALE 20.0f
#define INV_SCALE (1.0f/(QSCALE*QSCALE))
#define S2I 400           // QSCALE^2 as int

__device__ __align__(1024) signed char g_A[RM*DB];
__device__ __align__(1024) signed char g_B[RN*DB];
__device__ float g_valid[RM];
__device__ double g_acc;
__device__ unsigned g_done;

__device__ __forceinline__ uint32_t smem_u32(const void* p){
    uint32_t a; asm("{ .reg .u64 t; cvta.to.shared.u64 t, %1; cvt.u32.u64 %0, t; }":"=r"(a):"l"(p)); return a;
}
#define CPA16(d,s) asm volatile("cp.async.cg.shared.global [%0], [%1], 16;"::"r"(d),"l"(s):"memory")
#define CP_COMMIT() asm volatile("cp.async.commit_group;":::"memory")
#define CP_WAIT1()  asm volatile("cp.async.wait_group 1;":::"memory")

#define LDSM4(r0,r1,r2,r3,addr) \
    asm volatile("ldmatrix.sync.aligned.m8n8.x4.shared.b16 {%0,%1,%2,%3}, [%4];" \
        : "=r"(r0),"=r"(r1),"=r"(r2),"=r"(r3) : "r"(addr))

#define MMAS8(c,a,b0,b1) \
    asm volatile("mma.sync.aligned.m16n8k32.row.col.s32.s8.s8.s32 " \
        "{%0,%1,%2,%3},{%4,%5,%6,%7},{%8,%9},{%0,%1,%2,%3};" \
        : "+r"((c)[0]),"+r"((c)[1]),"+r"((c)[2]),"+r"((c)[3]) \
        : "r"((a)[0]),"r"((a)[1]),"r"((a)[2]),"r"((a)[3]),"r"(b0),"r"(b1))

// Load one 128-byte K-chunk of a 128x128 tile (A + B panels) into stage stg.
__device__ __forceinline__ void load_chunk(int q, int stg, int tid, uint32_t sb, int bid, int grid){
    int lt = q>>1, kc = q&1;
    int t = bid + lt*grid;
    int tm = t & (TILES_M-1), tn = t>>6;
    uint32_t st  = sb + SMEM0 + stg*STAGE_BYTES;
    uint32_t stB = st + STAGE_A;
    const signed char* Ag = g_A + (size_t)(tm*TM)*DB + kc*128;
    const signed char* Bg = g_B + (size_t)(tn*TN)*DB + kc*128;
    #pragma unroll
    for(int j=0;j<4;j++){                   // A: 1024 16B units
        int u = tid + j*NTHREADS;
        int r = u>>3, cc = u&7;
        uint32_t off = (cc*16) ^ ((r&7)<<4);
        CPA16(st + r*128 + off, Ag + (size_t)r*DB + cc*16);
    }
    #pragma unroll
    for(int j=0;j<4;j++){                   // B: 1024 16B units
        int u = tid + j*NTHREADS;
        int r = u>>3, cc = u&7;
        uint32_t off = (cc*16) ^ ((r&7)<<4);
        CPA16(stB + r*128 + off, Bg + (size_t)r*DB + cc*16);
    }
}

__global__ void __launch_bounds__(NTHREADS,2) frag_main(float* out){
    extern __shared__ char smem[];
    uint32_t sb = smem_u32(smem);
    int tid = threadIdx.x, wid = tid>>5, lane = tid&31;
    int bid = blockIdx.x, grid = gridDim.x;

    int m0 = (wid & 1)*64, n0 = (wid >> 1)*32;   // warp tile 64x32

    uint32_t perm = (lane&7)<<4;
    uint32_t halfoff = (lane>>4)*16;
    uint32_t rowA[4], rowB[2];
    #pragma unroll
    for(int f=0;f<4;f++) rowA[f] = (m0 + f*16 + (lane&15))*128;
    #pragma unroll
    for(int f=0;f<2;f++) rowB[f] = (n0 + f*16 + (lane&15))*128;

    int ntl = 0;
    for(int t=bid;t<NTILES;t+=grid) ntl++;
    int nch = ntl*2;

    int c[4][4][4];
    #pragma unroll
    for(int i=0;i<4;i++)
        #pragma unroll
        for(int j=0;j<4;j++)
            #pragma unroll
            for(int k=0;k<4;k++) c[i][j][k] = 0;

    float acc = 0.f;

    for(int q=0;q<2;q++){
        if(q<nch) load_chunk(q, q, tid, sb, bid, grid);
        CP_COMMIT();
    }

    int q = 0, cs = 0;  // consume stage
    for(int t=bid;t<NTILES;t+=grid){
        int tm = t & (TILES_M-1), tn = t>>6;
        #pragma unroll
        for(int kc=0;kc<2;kc++,q++){
            CP_WAIT1();                // chunk q resident
            __syncthreads();           // all warps done reading stage being refilled
            int ls = cs+2; if(ls>=NSTAGE) ls-=NSTAGE;
            if(q+2 < nch) load_chunk(q+2, ls, tid, sb, bid, grid);
            CP_COMMIT();

            uint32_t stA = sb + SMEM0 + cs*STAGE_BYTES;
            uint32_t stB = stA + STAGE_A;
            #pragma unroll
            for(int ks=0;ks<4;ks++){   // 4 x K=32
                uint32_t kx = (ks*32 + halfoff) ^ perm;
                uint32_t a[4][4], b[2][4];
                #pragma unroll
                for(int f=0;f<4;f++) LDSM4(a[f][0],a[f][1],a[f][2],a[f][3], stA + rowA[f] + kx);
                #pragma unroll
                for(int f=0;f<2;f++) LDSM4(b[f][0],b[f][1],b[f][2],b[f][3], stB + rowB[f] + kx);
                #pragma unroll
                for(int mf=0;mf<4;mf++)
                    #pragma unroll
                    for(int nb=0;nb<2;nb++){
                        MMAS8(c[mf][2*nb],   a[mf], b[nb][0], b[nb][2]);
                        MMAS8(c[mf][2*nb+1], a[mf], b[nb][1], b[nb][3]);
                    }
            }
            cs = cs+1; if(cs>=NSTAGE) cs -= NSTAGE;
        }

        // ---- integer epilogue: sum relu(S2 -/+ d) per validity row ----
        #pragma unroll
        for(int mf=0;mf<4;mf++){
            int growf = tm*TM + m0 + mf*16;
            int rb = growf >> 5;                  // warp-uniform batch of this 16-row block
            float v0 = g_valid[growf + (lane>>2)];
            float v1 = g_valid[growf + (lane>>2) + 8];
            int r0 = 0, r1 = 0;
            #pragma unroll
            for(int nb=0;nb<2;nb++){
                #pragma unroll
                for(int sub=0;sub<2;sub++){
                    int cb = (tn*TN + n0 + nb*16 + sub*8) >> 5;
                    int* cc = c[mf][2*nb+sub];
                    if(cb==rb){
                        r0 += max(S2I - cc[0], 0) + max(S2I - cc[1], 0);
                        r1 += max(S2I - cc[2], 0) + max(S2I - cc[3], 0);
                    } else {
                        r0 += max(S2I + cc[0], 0) + max(S2I + cc[1], 0);
                        r1 += max(S2I + cc[2], 0) + max(S2I + cc[3], 0);
                    }
                    cc[0]=0; cc[1]=0; cc[2]=0; cc[3]=0;
                }
            }
            acc += v0*(float)r0 + v1*(float)r1;
        }
    }

    // ---- CTA reduce + global accumulate + merged finalization ----
    #pragma unroll
    for(int o=16;o;o>>=1) acc += __shfl_xor_sync(0xffffffffu, acc, o);
    __shared__ float red[8];
    if(lane==0) red[wid] = acc;
    __syncthreads();
    if(tid==0){
        double s = 0.0;
        #pragma unroll
        for(int w=0;w<8;w++) s += (double)red[w];
        s *= (double)INV_SCALE;
        atomicAdd(&g_acc, s);
        __threadfence();
        unsigned prev = atomicAdd(&g_done, 1u);
        if(prev == gridDim.x - 1){
            __threadfence();
            double tot = *((volatile double*)&g_acc);
            out[0] = (float)(tot / 256.0);
        }
    }
}

// prep: fp32 -> int8 quantize (scale 20), validity mask, clear accumulators
__global__ void frag_prep(const float* __restrict__ face, const float* __restrict__ ner){
    int tid = threadIdx.x, wid = tid>>5, lane = tid&31;
    if(blockIdx.x==0 && tid==0){ g_acc = 0.0; g_done = 0u; }
    int row = blockIdx.x*8 + wid;
    bool isface = row < RM;
    const float* src = isface ? (face + (size_t)row*256) : (ner + (size_t)(row-RM)*256);
    signed char* dst = isface ? (g_A + (size_t)row*DB) : (g_B + (size_t)(row-RM)*DB);

    float4 v0 = ((const float4*)src)[lane];
    float4 v1 = ((const float4*)src)[lane+32];

    char4 q0, q1;
    #define QZ(x) (signed char)max(-127, min(127, __float2int_rn((x)*QSCALE)))
    q0.x=QZ(v0.x); q0.y=QZ(v0.y); q0.z=QZ(v0.z); q0.w=QZ(v0.w);
    q1.x=QZ(v1.x); q1.y=QZ(v1.y); q1.z=QZ(v1.z); q1.w=QZ(v1.w);
    #undef QZ
    ((char4*)dst)[lane]    = q0;
    ((char4*)dst)[lane+32] = q1;

    if(isface){
        float s = v0.x+v0.y+v0.z+v0.w + v1.x+v1.y+v1.z+v1.w;
        #pragma unroll
        for(int o=16;o;o>>=1) s += __shfl_xor_sync(0xffffffffu, s, o);
        if(lane==0) g_valid[row] = (s != 0.f) ? 1.f : 0.f;
    }
}

extern "C" void kernel_launch(void* const* d_in, const int* in_sizes, int n_in,
                              void* d_out, int out_size){
    const float* face = (const float*)d_in[0];
    const float* ner  = (const float*)d_in[1];
    float* out = (float*)d_out;

    cudaFuncSetAttribute(frag_main, cudaFuncAttributeMaxDynamicSharedMemorySize, SMEM_TOTAL);

    frag_prep<<<(RM+RN)/8, 256>>>(face, ner);
    frag_main<<<MAIN_GRID, NTHREADS, SMEM_TOTAL>>>(out);
}

// round 7
// speedup vs baseline: 2.0772x; 1.0705x over previous
#include <cuda_runtime.h>
#include <cuda_bf16.h>
#include <cstdint>

#define RM 8192
#define RN 8192
#define DB 256            // bytes per row (int8, D=256)
#define TM 128
#define TN 256
#define TILES_M 64
#define TILES_N 32
#define NTILES 2048
#define STAGE_A (TM*DB)               // 32 KB
#define STAGE_B (TN*DB)               // 64 KB
#define STAGE_BYTES (STAGE_A+STAGE_B) // 96 KB
#define SMEM0 1024
#define SMEM_TOTAL (SMEM0 + 2*STAGE_BYTES)   // 197632
#define MAIN_GRID 148
#define NTHREADS 256
#define QSCALE 20.0f
#define INV_SCALE (1.0f/(QSCALE*QSCALE))
#define S2I 400
#define S2I2 800

__device__ __align__(1024) signed char g_A[RM*DB];
__device__ __align__(1024) signed char g_B[RN*DB];
__device__ float g_valid[RM];
__device__ double g_acc;
__device__ unsigned g_done;

__device__ __forceinline__ uint32_t smem_u32(const void* p){
    uint32_t a; asm("{ .reg .u64 t; cvta.to.shared.u64 t, %1; cvt.u32.u64 %0, t; }":"=r"(a):"l"(p)); return a;
}
// SW128 swizzle for 256B rows (two 128B halves per row)
#define SWX(r,c) (((c)&0x80) | (((c)&0x7F) ^ (((r)&7)<<4)))

#define CPA16(d,s) asm volatile("cp.async.cg.shared.global [%0], [%1], 16;"::"r"(d),"l"(s):"memory")
#define CP_COMMIT() asm volatile("cp.async.commit_group;":::"memory")
#define CP_WAIT1()  asm volatile("cp.async.wait_group 1;":::"memory")

#define LDSM4(r0,r1,r2,r3,addr) \
    asm volatile("ldmatrix.sync.aligned.m8n8.x4.shared.b16 {%0,%1,%2,%3}, [%4];" \
        : "=r"(r0),"=r"(r1),"=r"(r2),"=r"(r3) : "r"(addr))

#define MMAS8(c,a,b0,b1) \
    asm volatile("mma.sync.aligned.m16n8k32.row.col.s32.s8.s8.s32 " \
        "{%0,%1,%2,%3},{%4,%5,%6,%7},{%8,%9},{%0,%1,%2,%3};" \
        : "+r"((c)[0]),"+r"((c)[1]),"+r"((c)[2]),"+r"((c)[3]) \
        : "r"((a)[0]),"r"((a)[1]),"r"((a)[2]),"r"((a)[3]),"r"(b0),"r"(b1))

// Load a full 128x256 tile (A panel + B panel, K=256) into stage stg.
__device__ __forceinline__ void load_tile(int t, int stg, int tid, uint32_t sb){
    int tm = t & (TILES_M-1), tn = t >> 6;
    uint32_t st  = sb + SMEM0 + stg*STAGE_BYTES;
    uint32_t stB = st + STAGE_A;
    const signed char* Ag = g_A + (size_t)(tm*TM)*DB;
    const signed char* Bg = g_B + (size_t)(tn*TN)*DB;
    #pragma unroll
    for(int j=0;j<8;j++){                     // A: 2048 16B units
        int u = tid + j*NTHREADS;
        int r = u>>4, c = (u&15)*16;
        CPA16(st + r*256 + SWX(r,c), Ag + (size_t)r*DB + c);
    }
    #pragma unroll
    for(int j=0;j<16;j++){                    // B: 4096 16B units
        int u = tid + j*NTHREADS;
        int r = u>>4, c = (u&15)*16;
        CPA16(stB + r*256 + SWX(r,c), Bg + (size_t)r*DB + c);
    }
}

__global__ void __launch_bounds__(NTHREADS,1) frag_main(float* out){
    extern __shared__ char smem[];
    uint32_t sb = smem_u32(smem);
    int tid = threadIdx.x, wid = tid>>5, lane = tid&31;
    int bid = blockIdx.x, grid = gridDim.x;

    int m0 = (wid & 1)*64, n0 = (wid >> 1)*64;   // warp tile 64x64

    uint32_t perm = (lane&7)<<4;
    uint32_t halfoff = (lane>>4)*16;
    uint32_t rowA[4], rowB[4];
    #pragma unroll
    for(int f=0;f<4;f++){
        rowA[f] = (m0 + f*16 + (lane&15))*256;
        rowB[f] = (n0 + f*16 + (lane&15))*256;
    }

    int c[4][8][4];
    #pragma unroll
    for(int i=0;i<4;i++)
        #pragma unroll
        for(int j=0;j<8;j++)
            #pragma unroll
            for(int k=0;k<4;k++) c[i][j][k] = S2I;

    float acc = 0.f;

    if(bid < NTILES) load_tile(bid, 0, tid, sb);
    CP_COMMIT();

    int lt = 0;
    for(int t=bid;t<NTILES;t+=grid,lt++){
        int tm = t & (TILES_M-1), tn = t >> 6;
        int stg = lt & 1;

        __syncthreads();                       // prev tile's compute fully drained
        if(t + grid < NTILES) load_tile(t + grid, stg^1, tid, sb);
        CP_COMMIT();
        CP_WAIT1();                            // this tile's stage resident (own thread)
        __syncthreads();                       // everyone's loads for this tile done

        // prefetch validity for this tile's rows
        float v0[4], v1[4];
        #pragma unroll
        for(int mf=0;mf<4;mf++){
            int growf = tm*TM + m0 + mf*16;
            v0[mf] = g_valid[growf + (lane>>2)];
            v1[mf] = g_valid[growf + (lane>>2) + 8];
        }

        uint32_t stA = sb + SMEM0 + stg*STAGE_BYTES;
        uint32_t stB = stA + STAGE_A;
        #pragma unroll
        for(int ks=0;ks<8;ks++){               // 8 x K=32
            uint32_t kb = ks*32 + halfoff;
            uint32_t kx = (kb & 0x80) | ((kb & 0x7F) ^ perm);
            uint32_t a[4][4], b[4][4];
            #pragma unroll
            for(int f=0;f<4;f++) LDSM4(a[f][0],a[f][1],a[f][2],a[f][3], stA + rowA[f] + kx);
            #pragma unroll
            for(int f=0;f<4;f++) LDSM4(b[f][0],b[f][1],b[f][2],b[f][3], stB + rowB[f] + kx);
            #pragma unroll
            for(int mf=0;mf<4;mf++)
                #pragma unroll
                for(int nb=0;nb<4;nb++){
                    MMAS8(c[mf][2*nb],   a[mf], b[nb][0], b[nb][2]);
                    MMAS8(c[mf][2*nb+1], a[mf], b[nb][1], b[nb][3]);
                }
        }

        // ---- epilogue: c was pre-biased with S2I, so off-diag = max(c,0) ----
        bool diag = ((tm >> 1) == tn);
        #pragma unroll
        for(int mf=0;mf<4;mf++){
            int r0 = 0, r1 = 0;
            if(!diag){
                #pragma unroll
                for(int j=0;j<8;j++){
                    int* cc = c[mf][j];
                    r0 += max(cc[0],0) + max(cc[1],0);
                    r1 += max(cc[2],0) + max(cc[3],0);
                    cc[0]=S2I; cc[1]=S2I; cc[2]=S2I; cc[3]=S2I;
                }
            } else {
                int growf = tm*TM + m0 + mf*16;
                int rb = growf >> 5;
                #pragma unroll
                for(int nb=0;nb<4;nb++){
                    #pragma unroll
                    for(int sub=0;sub<2;sub++){
                        int cb = (tn*TN + n0 + nb*16 + sub*8) >> 5;
                        int* cc = c[mf][2*nb+sub];
                        if(cb==rb){
                            r0 += max(S2I2 - cc[0], 0) + max(S2I2 - cc[1], 0);
                            r1 += max(S2I2 - cc[2], 0) + max(S2I2 - cc[3], 0);
                        } else {
                            r0 += max(cc[0],0) + max(cc[1],0);
                            r1 += max(cc[2],0) + max(cc[3],0);
                        }
                        cc[0]=S2I; cc[1]=S2I; cc[2]=S2I; cc[3]=S2I;
                    }
                }
            }
            acc += v0[mf]*(float)r0 + v1[mf]*(float)r1;
        }
    }

    // ---- CTA reduce + global accumulate + merged finalization ----
    #pragma unroll
    for(int o=16;o;o>>=1) acc += __shfl_xor_sync(0xffffffffu, acc, o);
    __shared__ float red[8];
    if(lane==0) red[wid] = acc;
    __syncthreads();
    if(tid==0){
        double s = 0.0;
        #pragma unroll
        for(int w=0;w<8;w++) s += (double)red[w];
        s *= (double)INV_SCALE;
        atomicAdd(&g_acc, s);
        __threadfence();
        unsigned prev = atomicAdd(&g_done, 1u);
        if(prev == gridDim.x - 1){
            __threadfence();
            double tot = *((volatile double*)&g_acc);
            out[0] = (float)(tot / 256.0);
        }
    }
}

// prep: fp32 -> int8 quantize (scale 20), validity mask, clear accumulators
__global__ void frag_prep(const float* __restrict__ face, const float* __restrict__ ner){
    int tid = threadIdx.x, wid = tid>>5, lane = tid&31;
    if(blockIdx.x==0 && tid==0){ g_acc = 0.0; g_done = 0u; }
    int row = blockIdx.x*8 + wid;
    bool isface = row < RM;
    const float* src = isface ? (face + (size_t)row*256) : (ner + (size_t)(row-RM)*256);
    signed char* dst = isface ? (g_A + (size_t)row*DB) : (g_B + (size_t)(row-RM)*DB);

    float4 v0 = ((const float4*)src)[lane];
    float4 v1 = ((const float4*)src)[lane+32];

    char4 q0, q1;
    #define QZ(x) (signed char)max(-127, min(127, __float2int_rn((x)*QSCALE)))
    q0.x=QZ(v0.x); q0.y=QZ(v0.y); q0.z=QZ(v0.z); q0.w=QZ(v0.w);
    q1.x=QZ(v1.x); q1.y=QZ(v1.y); q1.z=QZ(v1.z); q1.w=QZ(v1.w);
    #undef QZ
    ((char4*)dst)[lane]    = q0;
    ((char4*)dst)[lane+32] = q1;

    if(isface){
        float s = v0.x+v0.y+v0.z+v0.w + v1.x+v1.y+v1.z+v1.w;
        #pragma unroll
        for(int o=16;o;o>>=1) s += __shfl_xor_sync(0xffffffffu, s, o);
        if(lane==0) g_valid[row] = (s != 0.f) ? 1.f : 0.f;
    }
}

extern "C" void kernel_launch(void* const* d_in, const int* in_sizes, int n_in,
                              void* d_out, int out_size){
    const float* face = (const float*)d_in[0];
    const float* ner  = (const float*)d_in[1];
    float* out = (float*)d_out;

    cudaFuncSetAttribute(frag_main, cudaFuncAttributeMaxDynamicSharedMemorySize, SMEM_TOTAL);

    frag_prep<<<(RM+RN)/8, 256>>>(face, ner);
    frag_main<<<MAIN_GRID, NTHREADS, SMEM_TOTAL>>>(out);
}

// round 8
// speedup vs baseline: 2.1976x; 1.0580x over previous
#include <cuda_runtime.h>
#include <cuda_bf16.h>
#include <cstdint>

#define RM 8192
#define RN 8192
#define DB 256
#define TM 128
#define TN 256
#define TILES_N 32
#define STAGE_A (TM*DB)               // 32 KB
#define STAGE_B (TN*DB)               // 64 KB
#define STAGE_BYTES (STAGE_A+STAGE_B) // 96 KB
#define SMEM0 1024
#define SMEM_TOTAL (SMEM0 + 2*STAGE_BYTES)
#define MAIN_GRID 148
#define NTHREADS 256
#define QSCALE 20.0f
#define INV_SCALE (1.0f/(QSCALE*QSCALE))
#define S2I 400
#define S2I2 800

__device__ __align__(1024) signed char g_A[RM*DB];     // compacted face (int8)
__device__ __align__(1024) signed char g_Afull[RM*DB]; // quantized face, orig order
__device__ __align__(1024) signed char g_B[RN*DB];
__device__ int g_flag[RM];
__device__ int g_pos[RM];
__device__ int g_rb[RM];        // compacted row -> batch idx (-1 = pad)
__device__ int g_ntm;           // number of M tiles
__device__ double g_acc;
__device__ unsigned g_done;

__device__ __forceinline__ uint32_t smem_u32(const void* p){
    uint32_t a; asm("{ .reg .u64 t; cvta.to.shared.u64 t, %1; cvt.u32.u64 %0, t; }":"=r"(a):"l"(p)); return a;
}
#define SWX(r,c) (((c)&0x80) | (((c)&0x7F) ^ (((r)&7)<<4)))
#define CPA16(d,s) asm volatile("cp.async.cg.shared.global [%0], [%1], 16;"::"r"(d),"l"(s):"memory")
#define CP_COMMIT() asm volatile("cp.async.commit_group;":::"memory")
#define CP_WAIT1()  asm volatile("cp.async.wait_group 1;":::"memory")

#define LDSM4(r0,r1,r2,r3,addr) \
    asm volatile("ldmatrix.sync.aligned.m8n8.x4.shared.b16 {%0,%1,%2,%3}, [%4];" \
        : "=r"(r0),"=r"(r1),"=r"(r2),"=r"(r3) : "r"(addr))
#define MMAS8(c,a,b0,b1) \
    asm volatile("mma.sync.aligned.m16n8k32.row.col.s32.s8.s8.s32 " \
        "{%0,%1,%2,%3},{%4,%5,%6,%7},{%8,%9},{%0,%1,%2,%3};" \
        : "+r"((c)[0]),"+r"((c)[1]),"+r"((c)[2]),"+r"((c)[3]) \
        : "r"((a)[0]),"r"((a)[1]),"r"((a)[2]),"r"((a)[3]),"r"(b0),"r"(b1))

__device__ __forceinline__ void load_tile(int tm, int tn, int stg, int tid, uint32_t sb){
    uint32_t st  = sb + SMEM0 + stg*STAGE_BYTES;
    uint32_t stB = st + STAGE_A;
    const signed char* Ag = g_A + (size_t)(tm*TM)*DB;
    const signed char* Bg = g_B + (size_t)(tn*TN)*DB;
    #pragma unroll
    for(int j=0;j<8;j++){
        int u = tid + j*NTHREADS;
        int r = u>>4, cc = (u&15)*16;
        CPA16(st + r*256 + SWX(r,cc), Ag + (size_t)r*DB + cc);
    }
    #pragma unroll
    for(int j=0;j<16;j++){
        int u = tid + j*NTHREADS;
        int r = u>>4, cc = (u&15)*16;
        CPA16(stB + r*256 + SWX(r,cc), Bg + (size_t)r*DB + cc);
    }
}

__global__ void __launch_bounds__(NTHREADS,1) frag_main(float* out){
    extern __shared__ char smem[];
    uint32_t sb = smem_u32(smem);
    int tid = threadIdx.x, wid = tid>>5, lane = tid&31;
    int bid = blockIdx.x, grid = gridDim.x;

    int m0 = (wid & 1)*64, n0 = (wid >> 1)*64;
    uint32_t ntm = (uint32_t)g_ntm;
    uint32_t nt  = ntm * TILES_N;

    uint32_t perm = (lane&7)<<4;
    uint32_t halfoff = (lane>>4)*16;
    uint32_t rowA[4], rowB[4];
    #pragma unroll
    for(int f=0;f<4;f++){
        rowA[f] = (m0 + f*16 + (lane&15))*256;
        rowB[f] = (n0 + f*16 + (lane&15))*256;
    }

    int c[4][8][4];
    #pragma unroll
    for(int i=0;i<4;i++)
        #pragma unroll
        for(int j=0;j<8;j++)
            #pragma unroll
            for(int k=0;k<4;k++) c[i][j][k] = S2I;

    float acc = 0.f;

    if((uint32_t)bid < nt){
        uint32_t tn0 = (uint32_t)bid / ntm, tm0 = (uint32_t)bid - tn0*ntm;
        load_tile(tm0, tn0, 0, tid, sb);
    }
    CP_COMMIT();

    int lt = 0;
    for(uint32_t t=bid; t<nt; t+=grid, lt++){
        uint32_t tn = t / ntm, tm = t - tn*ntm;
        int stg = lt & 1;

        __syncthreads();
        uint32_t t2 = t + grid;
        if(t2 < nt){
            uint32_t tn2 = t2 / ntm, tm2 = t2 - tn2*ntm;
            load_tile(tm2, tn2, stg^1, tid, sb);
        }
        CP_COMMIT();
        CP_WAIT1();
        __syncthreads();

        // prefetch per-row batch indices (compacted)
        int rb0[4], rb1[4];
        #pragma unroll
        for(int mf=0;mf<4;mf++){
            int growf = tm*TM + m0 + mf*16;
            rb0[mf] = g_rb[growf + (lane>>2)];
            rb1[mf] = g_rb[growf + (lane>>2) + 8];
        }

        uint32_t stA = sb + SMEM0 + stg*STAGE_BYTES;
        uint32_t stB = stA + STAGE_A;
        #pragma unroll
        for(int ks=0;ks<8;ks++){
            uint32_t kb = ks*32 + halfoff;
            uint32_t kx = (kb & 0x80) | ((kb & 0x7F) ^ perm);
            uint32_t a[4][4], b[4][4];
            #pragma unroll
            for(int f=0;f<4;f++) LDSM4(a[f][0],a[f][1],a[f][2],a[f][3], stA + rowA[f] + kx);
            #pragma unroll
            for(int f=0;f<4;f++) LDSM4(b[f][0],b[f][1],b[f][2],b[f][3], stB + rowB[f] + kx);
            #pragma unroll
            for(int mf=0;mf<4;mf++)
                #pragma unroll
                for(int nb=0;nb<4;nb++){
                    MMAS8(c[mf][2*nb],   a[mf], b[nb][0], b[nb][2]);
                    MMAS8(c[mf][2*nb+1], a[mf], b[nb][1], b[nb][3]);
                }
        }

        // ---- epilogue: pre-biased ints, per-fragment diag vote ----
        int cb_lo = tn*8 + (n0>>5);          // warp covers 2 column batches
        int cb_hi = cb_lo + 1;
        #pragma unroll
        for(int mf=0;mf<4;mf++){
            int r0 = 0, r1 = 0;
            bool slow = __any_sync(0xffffffffu,
                 rb0[mf]==cb_lo || rb0[mf]==cb_hi || rb1[mf]==cb_lo || rb1[mf]==cb_hi);
            if(!slow){
                #pragma unroll
                for(int j=0;j<8;j++){
                    int* cc = c[mf][j];
                    r0 += max(cc[0],0) + max(cc[1],0);
                    r1 += max(cc[2],0) + max(cc[3],0);
                    cc[0]=S2I; cc[1]=S2I; cc[2]=S2I; cc[3]=S2I;
                }
            } else {
                #pragma unroll
                for(int nb=0;nb<4;nb++){
                    #pragma unroll
                    for(int sub=0;sub<2;sub++){
                        int cb = cb_lo + (nb>>1);
                        int* cc = c[mf][2*nb+sub];
                        bool p0 = (rb0[mf]==cb), p1 = (rb1[mf]==cb);
                        r0 += p0 ? (max(S2I2-cc[0],0)+max(S2I2-cc[1],0))
                                 : (max(cc[0],0)+max(cc[1],0));
                        r1 += p1 ? (max(S2I2-cc[2],0)+max(S2I2-cc[3],0))
                                 : (max(cc[2],0)+max(cc[3],0));
                        cc[0]=S2I; cc[1]=S2I; cc[2]=S2I; cc[3]=S2I;
                    }
                }
            }
            acc += (rb0[mf]>=0 ? (float)r0 : 0.f) + (rb1[mf]>=0 ? (float)r1 : 0.f);
        }
    }

    #pragma unroll
    for(int o=16;o;o>>=1) acc += __shfl_xor_sync(0xffffffffu, acc, o);
    __shared__ float red[8];
    if(lane==0) red[wid] = acc;
    __syncthreads();
    if(tid==0){
        double s = 0.0;
        #pragma unroll
        for(int w=0;w<8;w++) s += (double)red[w];
        s *= (double)INV_SCALE;
        atomicAdd(&g_acc, s);
        __threadfence();
        unsigned prev = atomicAdd(&g_done, 1u);
        if(prev == gridDim.x - 1){
            __threadfence();
            double tot = *((volatile double*)&g_acc);
            out[0] = (float)(tot / 256.0);
        }
    }
}

// prep1: quantize; face -> g_Afull + validity flag; ner -> g_B
__global__ void frag_prep(const float* __restrict__ face, const float* __restrict__ ner){
    int tid = threadIdx.x, wid = tid>>5, lane = tid&31;
    if(blockIdx.x==0 && tid==0){ g_acc = 0.0; g_done = 0u; }
    int row = blockIdx.x*8 + wid;
    bool isface = row < RM;
    const float* src = isface ? (face + (size_t)row*256) : (ner + (size_t)(row-RM)*256);
    signed char* dst = isface ? (g_Afull + (size_t)row*DB) : (g_B + (size_t)(row-RM)*DB);

    float4 v0 = ((const float4*)src)[lane];
    float4 v1 = ((const float4*)src)[lane+32];
    char4 q0, q1;
    #define QZ(x) (signed char)max(-127, min(127, __float2int_rn((x)*QSCALE)))
    q0.x=QZ(v0.x); q0.y=QZ(v0.y); q0.z=QZ(v0.z); q0.w=QZ(v0.w);
    q1.x=QZ(v1.x); q1.y=QZ(v1.y); q1.z=QZ(v1.z); q1.w=QZ(v1.w);
    #undef QZ
    ((char4*)dst)[lane]    = q0;
    ((char4*)dst)[lane+32] = q1;

    if(isface){
        float s = v0.x+v0.y+v0.z+v0.w + v1.x+v1.y+v1.z+v1.w;
        #pragma unroll
        for(int o=16;o;o>>=1) s += __shfl_xor_sync(0xffffffffu, s, o);
        if(lane==0) g_flag[row] = (s != 0.f) ? 1 : 0;
    }
}

// prep2: single-block exclusive scan of flags; pad-zero tail rows
__global__ void __launch_bounds__(1024,1) frag_scan(){
    __shared__ int ws[32];
    __shared__ int tot;
    int t = threadIdx.x, lane = t&31, w = t>>5;
    int f[8], s = 0;
    #pragma unroll
    for(int i=0;i<8;i++){ f[i] = g_flag[t*8+i]; s += f[i]; }
    int pre = s;
    #pragma unroll
    for(int o=1;o<32;o<<=1){ int v = __shfl_up_sync(0xffffffffu, pre, o); if(lane>=o) pre += v; }
    if(lane==31) ws[w] = pre;
    __syncthreads();
    if(w==0){
        int v = ws[lane];
        #pragma unroll
        for(int o=1;o<32;o<<=1){ int x = __shfl_up_sync(0xffffffffu, v, o); if(lane>=o) v += x; }
        ws[lane] = v;
    }
    __syncthreads();
    int base = (w>0 ? ws[w-1] : 0) + pre - s;
    int p = base;
    #pragma unroll
    for(int i=0;i<8;i++){ g_pos[t*8+i] = p; p += f[i]; }
    if(t==1023){ tot = p; g_ntm = (p + TM - 1)/TM; }
    __syncthreads();
    int count = tot, pad_end = ((count + TM - 1)/TM)*TM;
    for(int r = count + t; r < pad_end; r += 1024) g_rb[r] = -1;
    int units = (pad_end - count)*16;   // 16B units of pad row data
    int4 z = {0,0,0,0};
    int4* pz = (int4*)(g_A + (size_t)count*DB);
    for(int u = t; u < units; u += 1024) pz[u] = z;
}

// prep3: scatter valid face rows into compacted g_A + batch table
__global__ void frag_scatter(){
    int tid = threadIdx.x, wid = tid>>5, lane = tid&31;
    int row = blockIdx.x*8 + wid;
    if(row < RM && g_flag[row]){
        int pos = g_pos[row];
        if(lane < 16)
            ((int4*)(g_A + (size_t)pos*DB))[lane] = ((const int4*)(g_Afull + (size_t)row*DB))[lane];
        if(lane == 0) g_rb[pos] = row >> 5;
    }
}

extern "C" void kernel_launch(void* const* d_in, const int* in_sizes, int n_in,
                              void* d_out, int out_size){
    const float* face = (const float*)d_in[0];
    const float* ner  = (const float*)d_in[1];
    float* out = (float*)d_out;

    cudaFuncSetAttribute(frag_main, cudaFuncAttributeMaxDynamicSharedMemorySize, SMEM_TOTAL);

    frag_prep<<<(RM+RN)/8, 256>>>(face, ner);
    frag_scan<<<1, 1024>>>();
    frag_scatter<<<RM/8, 256>>>();
    frag_main<<<MAIN_GRID, NTHREADS, SMEM_TOTAL>>>(out);
}